// round 1
// baseline (speedup 1.0000x reference)
#include <cuda_runtime.h>

#define N_NODES 100000
#define FULL 0xFFFFFFFFu

// Scratch: __device__ globals (allocation-free). float4 for 16B-aligned vector atomics.
__device__ float4 g_t1[N_NODES * 16];    // feature @ W1      [N,64]
__device__ float4 g_agg1[N_NODES * 16];  // segment_sum       [N,64]
__device__ float4 g_g2[N_NODES * 4];     // relu(agg1+b1)@W2  [N,16]
__device__ float4 g_agg2[N_NODES * 4];   // segment_sum       [N,16]

// K1: t1 = feature @ W1 (warp per row, W1 staged in smem), and zero agg1.
__global__ void k1_gemm1(const float* __restrict__ feat, const float* __restrict__ W1) {
    __shared__ float Ws[64 * 64];
    for (int i = threadIdx.x; i < 64 * 64; i += blockDim.x) Ws[i] = W1[i];
    __syncthreads();
    int row  = (blockIdx.x * blockDim.x + threadIdx.x) >> 5;
    int lane = threadIdx.x & 31;
    if (row >= N_NODES) return;
    const float* f = feat + row * 64;
    float f_lo = f[lane];
    float f_hi = f[lane + 32];
    float acc0 = 0.f, acc1 = 0.f;
#pragma unroll
    for (int k = 0; k < 32; k++) {
        float a = __shfl_sync(FULL, f_lo, k);
        acc0 += a * Ws[k * 64 + lane];
        acc1 += a * Ws[k * 64 + 32 + lane];
    }
#pragma unroll
    for (int k = 0; k < 32; k++) {
        float a = __shfl_sync(FULL, f_hi, k);
        acc0 += a * Ws[(k + 32) * 64 + lane];
        acc1 += a * Ws[(k + 32) * 64 + 32 + lane];
    }
    float* t1 = (float*)g_t1;
    float* ag = (float*)g_agg1;
    t1[row * 64 + lane]      = acc0;
    t1[row * 64 + 32 + lane] = acc1;
    ag[row * 64 + lane]      = 0.f;
    ag[row * 64 + 32 + lane] = 0.f;
}

// K2: per-edge scatter-add of 64-wide rows. One thread per (edge, float4 chunk).
__global__ void k2_scatter64(const int* __restrict__ src, const int* __restrict__ dst, int total) {
    int idx = blockIdx.x * blockDim.x + threadIdx.x;
    if (idx >= total) return;
    int e = idx >> 4;
    int c = idx & 15;
    int s = __ldg(src + e);
    int d = __ldg(dst + e);
    float4 v = g_t1[s * 16 + c];
    float4* p = &g_agg1[d * 16 + c];
    asm volatile("red.global.add.v4.f32 [%0], {%1,%2,%3,%4};"
                 :: "l"(p), "f"(v.x), "f"(v.y), "f"(v.z), "f"(v.w) : "memory");
}

// K3: g2 = relu(agg1 + b1) @ W2 (warp per row), and zero agg2.
__global__ void k3_fused(const float* __restrict__ b1, const float* __restrict__ W2) {
    __shared__ float W2s[64 * 16];
    __shared__ float b1s[64];
    for (int i = threadIdx.x; i < 64 * 16; i += blockDim.x) W2s[i] = W2[i];
    if (threadIdx.x < 64) b1s[threadIdx.x] = b1[threadIdx.x];
    __syncthreads();
    int row  = (blockIdx.x * blockDim.x + threadIdx.x) >> 5;
    int lane = threadIdx.x & 31;
    if (row >= N_NODES) return;
    const float* ag = (const float*)g_agg1;
    float h_lo = fmaxf(ag[row * 64 + lane] + b1s[lane], 0.f);
    float h_hi = fmaxf(ag[row * 64 + 32 + lane] + b1s[lane + 32], 0.f);
    int c    = lane & 15;
    int half = lane >> 4;   // lanes 0-15 cover k=0..31, lanes 16-31 cover k=32..63
    float acc = 0.f;
#pragma unroll
    for (int kk = 0; kk < 32; kk++) {
        float a = __shfl_sync(FULL, h_lo, kk);
        float b = __shfl_sync(FULL, h_hi, kk);
        float hk = half ? b : a;
        acc += hk * W2s[(half * 32 + kk) * 16 + c];
    }
    acc += __shfl_down_sync(FULL, acc, 16);
    if (lane < 16) {
        ((float*)g_g2)[row * 16 + c]   = acc;
        ((float*)g_agg2)[row * 16 + c] = 0.f;
    }
}

// K4: per-edge scatter-add of 16-wide rows. One thread per (edge, float4 chunk).
__global__ void k4_scatter16(const int* __restrict__ src, const int* __restrict__ dst, int total) {
    int idx = blockIdx.x * blockDim.x + threadIdx.x;
    if (idx >= total) return;
    int e = idx >> 2;
    int c = idx & 3;
    int s = __ldg(src + e);
    int d = __ldg(dst + e);
    float4 v = g_g2[s * 4 + c];
    float4* p = &g_agg2[d * 4 + c];
    asm volatile("red.global.add.v4.f32 [%0], {%1,%2,%3,%4};"
                 :: "l"(p), "f"(v.x), "f"(v.y), "f"(v.z), "f"(v.w) : "memory");
}

// K5: out = softmax(agg2 + b2), one thread per node.
__global__ void k5_softmax(const float* __restrict__ b2, float* __restrict__ out) {
    int n = blockIdx.x * blockDim.x + threadIdx.x;
    if (n >= N_NODES) return;
    float x[16];
#pragma unroll
    for (int i = 0; i < 4; i++) {
        float4 v = g_agg2[n * 4 + i];
        x[i * 4 + 0] = v.x + __ldg(b2 + i * 4 + 0);
        x[i * 4 + 1] = v.y + __ldg(b2 + i * 4 + 1);
        x[i * 4 + 2] = v.z + __ldg(b2 + i * 4 + 2);
        x[i * 4 + 3] = v.w + __ldg(b2 + i * 4 + 3);
    }
    float m = x[0];
#pragma unroll
    for (int j = 1; j < 16; j++) m = fmaxf(m, x[j]);
    float s = 0.f;
#pragma unroll
    for (int j = 0; j < 16; j++) { x[j] = expf(x[j] - m); s += x[j]; }
    float inv = 1.f / s;
#pragma unroll
    for (int j = 0; j < 16; j++) out[n * 16 + j] = x[j] * inv;
}

extern "C" void kernel_launch(void* const* d_in, const int* in_sizes, int n_in,
                              void* d_out, int out_size) {
    const float* feature = (const float*)d_in[0];
    const float* W1      = (const float*)d_in[1];
    const float* b1      = (const float*)d_in[2];
    const float* W2      = (const float*)d_in[3];
    const float* b2      = (const float*)d_in[4];
    const int*   src     = (const int*)d_in[5];
    const int*   dst     = (const int*)d_in[6];
    float*       out     = (float*)d_out;
    int E = in_sizes[5];

    int rowBlocks = (N_NODES * 32 + 255) / 256;
    k1_gemm1<<<rowBlocks, 256>>>(feature, W1);

    int total1 = E * 16;
    k2_scatter64<<<(total1 + 255) / 256, 256>>>(src, dst, total1);

    k3_fused<<<rowBlocks, 256>>>(b1, W2);

    int total2 = E * 4;
    k4_scatter16<<<(total2 + 255) / 256, 256>>>(src, dst, total2);

    k5_softmax<<<(N_NODES + 255) / 256, 256>>>(b2, out);
}

// round 2
// speedup vs baseline: 1.2051x; 1.2051x over previous
#include <cuda_runtime.h>

#define N_NODES 100000
#define E_MAX   1600000
#define NB      98
#define NPAD    (NB * 1024)   // 100352 >= N_NODES
#define FULL    0xFFFFFFFFu

// Scratch (allocation-free __device__ globals)
__device__ float g_t1[N_NODES * 64];     // feature @ W1
__device__ float g_g2[N_NODES * 16];     // relu(agg1+b1) @ W2
__device__ int   g_counts[NPAD];         // in-degree histogram (padded, zeroed)
__device__ int   g_offsets[NPAD];        // exclusive prefix sum
__device__ int   g_cursor[NPAD];         // fill cursors
__device__ int   g_blockTotal[NB];
__device__ int   g_blockOffset[NB];
__device__ int   g_edge_src[E_MAX];      // CSR: src ids grouped by dst

// K1: t1 = feature @ W1 (warp per row, W1 in smem).
__global__ void k1_gemm1(const float* __restrict__ feat, const float* __restrict__ W1) {
    __shared__ float Ws[64 * 64];
    for (int i = threadIdx.x; i < 64 * 64; i += blockDim.x) Ws[i] = W1[i];
    __syncthreads();
    int row  = (blockIdx.x * blockDim.x + threadIdx.x) >> 5;
    int lane = threadIdx.x & 31;
    if (row >= N_NODES) return;
    const float* f = feat + row * 64;
    float f_lo = f[lane];
    float f_hi = f[lane + 32];
    float acc0 = 0.f, acc1 = 0.f;
#pragma unroll
    for (int k = 0; k < 32; k++) {
        float a = __shfl_sync(FULL, f_lo, k);
        acc0 += a * Ws[k * 64 + lane];
        acc1 += a * Ws[k * 64 + 32 + lane];
    }
#pragma unroll
    for (int k = 0; k < 32; k++) {
        float a = __shfl_sync(FULL, f_hi, k);
        acc0 += a * Ws[(k + 32) * 64 + lane];
        acc1 += a * Ws[(k + 32) * 64 + 32 + lane];
    }
    g_t1[row * 64 + lane]      = acc0;
    g_t1[row * 64 + 32 + lane] = acc1;
}

// CSR build step 0: zero padded histogram.
__global__ void k_zero() {
    int i = blockIdx.x * blockDim.x + threadIdx.x;
    if (i < NPAD) g_counts[i] = 0;
}

// CSR build step 1: in-degree histogram.
__global__ void k_hist(const int* __restrict__ dst, int E) {
    int e = blockIdx.x * blockDim.x + threadIdx.x;
    if (e < E) atomicAdd(&g_counts[dst[e]], 1);
}

// CSR build step 2a: per-1024-chunk totals.
__global__ void k_passA() {
    __shared__ int sh[256];
    int b = blockIdx.x, t = threadIdx.x;
    int sum = 0;
#pragma unroll
    for (int i = 0; i < 4; i++) sum += g_counts[b * 1024 + t + i * 256];
    sh[t] = sum;
    __syncthreads();
    for (int s = 128; s > 0; s >>= 1) {
        if (t < s) sh[t] += sh[t + s];
        __syncthreads();
    }
    if (t == 0) g_blockTotal[b] = sh[0];
}

// CSR build step 2b: exclusive scan of NB chunk totals (single block).
__global__ void k_passB() {
    __shared__ int sh[NB];
    int t = threadIdx.x;
    if (t < NB) sh[t] = g_blockTotal[t];
    __syncthreads();
    if (t == 0) {
        int run = 0;
        for (int i = 0; i < NB; i++) { int v = sh[i]; sh[i] = run; run += v; }
    }
    __syncthreads();
    if (t < NB) g_blockOffset[t] = sh[t];
}

// CSR build step 2c: per-chunk scan + chunk offset -> exclusive offsets, init cursor.
__global__ void k_passC() {
    __shared__ int sh[1024];
    int b = blockIdx.x, t = threadIdx.x;
    int idx = b * 1024 + t;
    int c = g_counts[idx];
    sh[t] = c;
    __syncthreads();
    for (int d = 1; d < 1024; d <<= 1) {
        int v = (t >= d) ? sh[t - d] : 0;
        __syncthreads();
        sh[t] += v;
        __syncthreads();
    }
    int off = g_blockOffset[b] + sh[t] - c;   // exclusive
    g_offsets[idx] = off;
    g_cursor[idx]  = off;
}

// CSR build step 3: scatter src ids grouped by dst.
__global__ void k_fill(const int* __restrict__ src, const int* __restrict__ dst, int E) {
    int e = blockIdx.x * blockDim.x + threadIdx.x;
    if (e < E) {
        int d = dst[e];
        int pos = atomicAdd(&g_cursor[d], 1);
        g_edge_src[pos] = src[e];
    }
}

// K_agg1: gather-aggregate t1 rows per dst node, then relu(+b1) @ W2 -> g2. Warp per node.
__global__ void k_agg1_fused(const float* __restrict__ b1, const float* __restrict__ W2) {
    __shared__ float W2s[64 * 16];
    __shared__ float b1s[64];
    for (int i = threadIdx.x; i < 64 * 16; i += blockDim.x) W2s[i] = W2[i];
    if (threadIdx.x < 64) b1s[threadIdx.x] = b1[threadIdx.x];
    __syncthreads();
    int n    = (blockIdx.x * blockDim.x + threadIdx.x) >> 5;
    int lane = threadIdx.x & 31;
    if (n >= N_NODES) return;

    int start = g_offsets[n];
    int deg   = g_counts[n];
    float acc0 = 0.f, acc1 = 0.f;
    int j = 0;
    for (; j + 1 < deg; j += 2) {
        int s0 = __ldg(&g_edge_src[start + j]);
        int s1 = __ldg(&g_edge_src[start + j + 1]);
        float a0 = __ldg(&g_t1[s0 * 64 + lane]);
        float a1 = __ldg(&g_t1[s0 * 64 + 32 + lane]);
        float c0 = __ldg(&g_t1[s1 * 64 + lane]);
        float c1 = __ldg(&g_t1[s1 * 64 + 32 + lane]);
        acc0 += a0 + c0;
        acc1 += a1 + c1;
    }
    if (j < deg) {
        int s0 = __ldg(&g_edge_src[start + j]);
        acc0 += __ldg(&g_t1[s0 * 64 + lane]);
        acc1 += __ldg(&g_t1[s0 * 64 + 32 + lane]);
    }

    float h_lo = fmaxf(acc0 + b1s[lane], 0.f);
    float h_hi = fmaxf(acc1 + b1s[lane + 32], 0.f);
    int c    = lane & 15;
    int half = lane >> 4;
    float acc = 0.f;
#pragma unroll
    for (int kk = 0; kk < 32; kk++) {
        float a = __shfl_sync(FULL, h_lo, kk);
        float b = __shfl_sync(FULL, h_hi, kk);
        float hk = half ? b : a;
        acc += hk * W2s[(half * 32 + kk) * 16 + c];
    }
    acc += __shfl_down_sync(FULL, acc, 16);
    if (lane < 16) g_g2[n * 16 + c] = acc;
}

// K_agg2: gather-aggregate g2 per dst node (16 lanes/node), + b2, softmax -> out.
__global__ void k_agg2_fused(const float* __restrict__ b2, float* __restrict__ out) {
    int warp = (blockIdx.x * blockDim.x + threadIdx.x) >> 5;
    int lane = threadIdx.x & 31;
    int grp  = lane >> 4;          // 0 or 1: two nodes per warp
    int l    = lane & 15;
    int n    = warp * 2 + grp;
    if (n >= N_NODES) return;

    int start = g_offsets[n];
    int deg   = g_counts[n];
    float acc = 0.f;
    int j = 0;
    for (; j + 1 < deg; j += 2) {
        int s0 = __ldg(&g_edge_src[start + j]);
        int s1 = __ldg(&g_edge_src[start + j + 1]);
        acc += __ldg(&g_g2[s0 * 16 + l]) + __ldg(&g_g2[s1 * 16 + l]);
    }
    if (j < deg) {
        int s0 = __ldg(&g_edge_src[start + j]);
        acc += __ldg(&g_g2[s0 * 16 + l]);
    }
    __syncwarp();
    float x = acc + __ldg(&b2[l]);
    float m = x;
#pragma unroll
    for (int off = 8; off; off >>= 1) m = fmaxf(m, __shfl_xor_sync(FULL, m, off));
    float e = expf(x - m);
    float s = e;
#pragma unroll
    for (int off = 8; off; off >>= 1) s += __shfl_xor_sync(FULL, s, off);
    out[n * 16 + l] = e / s;
}

extern "C" void kernel_launch(void* const* d_in, const int* in_sizes, int n_in,
                              void* d_out, int out_size) {
    const float* feature = (const float*)d_in[0];
    const float* W1      = (const float*)d_in[1];
    const float* b1      = (const float*)d_in[2];
    const float* W2      = (const float*)d_in[3];
    const float* b2      = (const float*)d_in[4];
    const int*   src     = (const int*)d_in[5];
    const int*   dst     = (const int*)d_in[6];
    float*       out     = (float*)d_out;
    int E = in_sizes[5];

    int rowBlocks = (N_NODES * 32 + 255) / 256;
    k1_gemm1<<<rowBlocks, 256>>>(feature, W1);

    k_zero<<<(NPAD + 255) / 256, 256>>>();
    k_hist<<<(E + 255) / 256, 256>>>(dst, E);
    k_passA<<<NB, 256>>>();
    k_passB<<<1, 128>>>();
    k_passC<<<NB, 1024>>>();
    k_fill<<<(E + 255) / 256, 256>>>(src, dst, E);

    k_agg1_fused<<<rowBlocks, 256>>>(b1, W2);
    k_agg2_fused<<<(N_NODES * 16 + 255) / 256, 256>>>(b2, out);
}